// round 3
// baseline (speedup 1.0000x reference)
#include <cuda_runtime.h>
#include <math.h>

// Problem dims (compile-time constants)
#define BB   512     // batch
#define IN_  256
#define HH   512
#define NS_  4
#define SS_  128
#define CS_  128
#define KC   1280    // IN + NS*CS + H = 256 + 512 + 512 (combined GEMM-h K)

// ---------------------------------------------------------------------------
// Scratch (no allocations allowed -> __device__ globals)
// ---------------------------------------------------------------------------
__device__ __align__(16) float g_X [BB * KC];          // [inputs | top | core]   (512 x 1280)
__device__ __align__(16) float g_Wc[HH * KC];          // [W_ih | W_hh]           (512 x 1280)
__device__ __align__(16) float g_bc[HH];               // b_ih + b_hh
__device__ __align__(16) float g_push[BB * NS_ * CS_]; // (512 x 512)
__device__ __align__(16) float g_probs[BB * NS_ * 3];

// ---------------------------------------------------------------------------
// Kernel 0: assemble X, Wc, bc
// ---------------------------------------------------------------------------
__global__ void prep_kernel(const float* __restrict__ inputs,
                            const float* __restrict__ stacks,
                            const float* __restrict__ core,
                            const float* __restrict__ W_ih,
                            const float* __restrict__ W_hh,
                            const float* __restrict__ b_ih,
                            const float* __restrict__ b_hh) {
    const int NX = BB * KC;
    const int NW = HH * KC;
    int idx = blockIdx.x * blockDim.x + threadIdx.x;
    if (idx < NX) {
        int b = idx / KC, k = idx % KC;
        float v;
        if (k < IN_) {
            v = inputs[b * IN_ + k];
        } else if (k < IN_ + NS_ * CS_) {
            int c = k - IN_;                       // 0..511
            int ns = c >> 7, cs = c & 127;
            v = stacks[((b * NS_ + ns) * SS_) * CS_ + cs];  // stacks[b][ns][0][cs]
        } else {
            v = core[b * HH + (k - IN_ - NS_ * CS_)];
        }
        g_X[idx] = v;
    } else if (idx < NX + NW) {
        int j = idx - NX;
        int n = j / KC, k = j % KC;
        g_Wc[j] = (k < IN_ + NS_ * CS_) ? W_ih[n * (IN_ + NS_ * CS_) + k]
                                        : W_hh[n * HH + (k - IN_ - NS_ * CS_)];
    } else if (idx < NX + NW + HH) {
        int n = idx - NX - NW;
        g_bc[n] = b_ih[n] + b_hh[n];
    }
}

// ---------------------------------------------------------------------------
// Tiled fp32 GEMM: C[M=512, N=512] = A[M,K] @ W[N,K]^T (+bias, optional tanh)
// BM=32, BN=64, BK=32, 256 threads, each thread 2x4 outputs.
// grid = (N/64=8, M/32=16) = 128 CTAs -> ~1 wave across the chip.
// ---------------------------------------------------------------------------
#define BM 32
#define BN 64
#define BKk 32

template <int ACT>
__global__ void __launch_bounds__(256)
gemm_kernel(const float* __restrict__ A, const float* __restrict__ W,
            const float* __restrict__ bias, float* __restrict__ C, int K) {
    __shared__ float As[BKk][BM + 4];
    __shared__ float Bs[BKk][BN + 4];

    const int tid = threadIdx.x;
    const int m0 = blockIdx.y * BM;
    const int n0 = blockIdx.x * BN;
    const int tx = tid & 15;       // 16 cols of threads (x4 outputs)
    const int ty = tid >> 4;       // 16 rows of threads (x2 outputs)

    float acc[2][4] = {};

    const int lr = tid >> 3;            // 0..31  (tile row for loads)
    const int lc = (tid & 7) << 2;      // 0,4,...,28 (k offset, float4)

    for (int k0 = 0; k0 < K; k0 += BKk) {
        // A tile: 32 x 32 floats = 256 float4, 1 per thread
        {
            float4 v = *(const float4*)(A + (m0 + lr) * K + k0 + lc);
            As[lc + 0][lr] = v.x; As[lc + 1][lr] = v.y;
            As[lc + 2][lr] = v.z; As[lc + 3][lr] = v.w;
        }
        // W tile: 64 x 32 floats = 512 float4, 2 per thread
        {
            float4 v = *(const float4*)(W + (n0 + lr) * K + k0 + lc);
            Bs[lc + 0][lr] = v.x; Bs[lc + 1][lr] = v.y;
            Bs[lc + 2][lr] = v.z; Bs[lc + 3][lr] = v.w;
            float4 u = *(const float4*)(W + (n0 + lr + 32) * K + k0 + lc);
            Bs[lc + 0][lr + 32] = u.x; Bs[lc + 1][lr + 32] = u.y;
            Bs[lc + 2][lr + 32] = u.z; Bs[lc + 3][lr + 32] = u.w;
        }
        __syncthreads();

        #pragma unroll
        for (int kk = 0; kk < BKk; ++kk) {
            float a0 = As[kk][ty * 2 + 0];
            float a1 = As[kk][ty * 2 + 1];
            float b0 = Bs[kk][tx * 4 + 0];
            float b1 = Bs[kk][tx * 4 + 1];
            float b2 = Bs[kk][tx * 4 + 2];
            float b3 = Bs[kk][tx * 4 + 3];
            acc[0][0] = fmaf(a0, b0, acc[0][0]);
            acc[0][1] = fmaf(a0, b1, acc[0][1]);
            acc[0][2] = fmaf(a0, b2, acc[0][2]);
            acc[0][3] = fmaf(a0, b3, acc[0][3]);
            acc[1][0] = fmaf(a1, b0, acc[1][0]);
            acc[1][1] = fmaf(a1, b1, acc[1][1]);
            acc[1][2] = fmaf(a1, b2, acc[1][2]);
            acc[1][3] = fmaf(a1, b3, acc[1][3]);
        }
        __syncthreads();
    }

    #pragma unroll
    for (int tm = 0; tm < 2; ++tm) {
        int m = m0 + ty * 2 + tm;
        #pragma unroll
        for (int tn = 0; tn < 4; ++tn) {
            int n = n0 + tx * 4 + tn;
            float v = acc[tm][tn] + bias[n];
            if (ACT) v = tanhf(v);
            C[m * HH + n] = v;
        }
    }
}

// ---------------------------------------------------------------------------
// Act kernel: per-batch 12 logits + ONE softmax over ALL 12 logits
// (reference applies softmax(axis=-1) to shape (B, 12) BEFORE reshape to
//  (B, NS, 3) -> joint normalization over all 12, not per-group-of-3)
// ---------------------------------------------------------------------------
__global__ void act_kernel(const float* __restrict__ h,
                           const float* __restrict__ W_act,
                           const float* __restrict__ b_act,
                           float* __restrict__ probs) {
    const int b = blockIdx.x;
    __shared__ float hs[HH];
    __shared__ float logits[NS_ * 3];

    for (int i = threadIdx.x; i < HH; i += 128) hs[i] = h[b * HH + i];
    __syncthreads();

    const int warp = threadIdx.x >> 5;
    const int lane = threadIdx.x & 31;
    for (int r = warp; r < NS_ * 3; r += 4) {
        float s = 0.f;
        for (int k = lane; k < HH; k += 32) s = fmaf(hs[k], W_act[r * HH + k], s);
        #pragma unroll
        for (int o = 16; o > 0; o >>= 1) s += __shfl_xor_sync(0xffffffffu, s, o);
        if (lane == 0) logits[r] = s + b_act[r];
    }
    __syncthreads();

    if (threadIdx.x == 0) {
        float mx = -INFINITY;
        #pragma unroll
        for (int i = 0; i < NS_ * 3; ++i) mx = fmaxf(mx, logits[i]);
        float sum = 0.f;
        float e[NS_ * 3];
        #pragma unroll
        for (int i = 0; i < NS_ * 3; ++i) { e[i] = expf(logits[i] - mx); sum += e[i]; }
        float inv = 1.f / sum;
        #pragma unroll
        for (int i = 0; i < NS_ * 3; ++i) probs[b * NS_ * 3 + i] = e[i] * inv;
    }
}

// ---------------------------------------------------------------------------
// Stack update: one block per (b, ns), thread = cs, sliding 3-register window
//   new[0] = pa*push + po*S[1] + no*S[0]
//   new[i] = pa*S[i-1] + po*S[i+1] + no*S[i]   (S[SS] = 0)
// Streams 268 MB total -> HBM-bound kernel.
// ---------------------------------------------------------------------------
__global__ void __launch_bounds__(CS_)
stack_kernel(const float* __restrict__ stacks,
             const float* __restrict__ push,
             const float* __restrict__ probs,
             float* __restrict__ out) {
    const int g  = blockIdx.x;          // b*NS + ns
    const int cs = threadIdx.x;

    const float pa = probs[g * 3 + 0];
    const float po = probs[g * 3 + 1];
    const float no = probs[g * 3 + 2];

    const float* S = stacks + (size_t)g * SS_ * CS_ + cs;
    float*       O = out    + (size_t)g * SS_ * CS_ + cs;

    const float pu = push[g * CS_ + cs];

    float cur = S[0];
    float nxt = S[CS_];
    O[0] = fmaf(pa, pu, fmaf(po, nxt, no * cur));

    #pragma unroll 8
    for (int i = 1; i < SS_; ++i) {
        float prev = cur;
        cur = nxt;
        nxt = (i + 1 < SS_) ? S[(i + 1) * CS_] : 0.f;
        O[i * CS_] = fmaf(pa, prev, fmaf(po, nxt, no * cur));
    }
}

// ---------------------------------------------------------------------------
// Launch
//   inputs order: inputs, stacks, core_state, W_ih, b_ih, W_hh, b_hh,
//                 W_push, b_push, W_act, b_act
//   output: h (B*H floats) followed by new_stacks (B*NS*SS*CS floats)
// ---------------------------------------------------------------------------
extern "C" void kernel_launch(void* const* d_in, const int* in_sizes, int n_in,
                              void* d_out, int out_size) {
    const float* inputs  = (const float*)d_in[0];
    const float* stacks  = (const float*)d_in[1];
    const float* core    = (const float*)d_in[2];
    const float* W_ih    = (const float*)d_in[3];
    const float* b_ih    = (const float*)d_in[4];
    const float* W_hh    = (const float*)d_in[5];
    const float* b_hh    = (const float*)d_in[6];
    const float* W_push  = (const float*)d_in[7];
    const float* b_push  = (const float*)d_in[8];
    const float* W_act   = (const float*)d_in[9];
    const float* b_act   = (const float*)d_in[10];

    float* out = (float*)d_out;
    float* h_out      = out;               // (B, H)
    float* stacks_out = out + BB * HH;     // (B, NS, SS, CS)

    float *pX, *pWc, *pbc, *ppush, *pprobs;
    cudaGetSymbolAddress((void**)&pX,     g_X);
    cudaGetSymbolAddress((void**)&pWc,    g_Wc);
    cudaGetSymbolAddress((void**)&pbc,    g_bc);
    cudaGetSymbolAddress((void**)&ppush,  g_push);
    cudaGetSymbolAddress((void**)&pprobs, g_probs);

    // 0) assemble X, Wc, bc
    {
        int total = BB * KC + HH * KC + HH;
        prep_kernel<<<(total + 255) / 256, 256>>>(inputs, stacks, core,
                                                  W_ih, W_hh, b_ih, b_hh);
    }

    // 1) h = tanh(X @ Wc^T + bc)      grid (8, 16)
    {
        dim3 grid(HH / BN, BB / BM);
        gemm_kernel<1><<<grid, 256>>>(pX, pWc, pbc, h_out, KC);
    }

    // 2) push = h @ W_push^T + b_push
    {
        dim3 grid(HH / BN, BB / BM);
        gemm_kernel<0><<<grid, 256>>>(h_out, W_push, b_push, ppush, HH);
    }

    // 3) act logits + joint softmax over 12
    act_kernel<<<BB, 128>>>(h_out, W_act, b_act, pprobs);

    // 4) stack shift update
    stack_kernel<<<BB * NS_, CS_>>>(stacks, ppush, pprobs, stacks_out);
}

// round 4
// speedup vs baseline: 1.1100x; 1.1100x over previous
#include <cuda_runtime.h>
#include <math.h>

#define BB   512
#define IN_  256
#define HH   512
#define NS_  4
#define SS_  128
#define CS_  128
#define KC   1280          // IN + NS*CS + H
#define NPA  576           // 512 push rows + 12 act rows + 52 zero pad

// ---------------------------------------------------------------------------
// Scratch
// ---------------------------------------------------------------------------
__device__ __align__(16) float g_X   [BB * KC];
__device__ __align__(16) float g_Wc  [HH * KC];
__device__ __align__(16) float g_bc  [HH];
__device__ __align__(16) float g_Wpa [NPA * HH];
__device__ __align__(16) float g_bpa [NPA];
__device__ __align__(16) float g_push[BB * NS_ * CS_];
__device__ __align__(16) float g_logits[BB * 12];

// ---------------------------------------------------------------------------
// prep: assemble X=[inputs|top|core], Wc=[W_ih|W_hh], bc=b_ih+b_hh,
//       Wpa=[W_push;W_act;0], bpa=[b_push;b_act;0]
// ---------------------------------------------------------------------------
__global__ void prep_kernel(const float* __restrict__ inputs,
                            const float* __restrict__ stacks,
                            const float* __restrict__ core,
                            const float* __restrict__ W_ih,
                            const float* __restrict__ W_hh,
                            const float* __restrict__ b_ih,
                            const float* __restrict__ b_hh,
                            const float* __restrict__ W_push,
                            const float* __restrict__ b_push,
                            const float* __restrict__ W_act,
                            const float* __restrict__ b_act) {
    const int NX = BB * KC;
    const int NW = HH * KC;
    const int NWPA = NPA * HH;
    int idx = blockIdx.x * blockDim.x + threadIdx.x;
    if (idx < NX) {
        int b = idx / KC, k = idx % KC;
        float v;
        if (k < IN_) {
            v = inputs[b * IN_ + k];
        } else if (k < IN_ + NS_ * CS_) {
            int c = k - IN_;
            int ns = c >> 7, cs = c & 127;
            v = stacks[((b * NS_ + ns) * SS_) * CS_ + cs];   // stacks[b][ns][0][cs]
        } else {
            v = core[b * HH + (k - IN_ - NS_ * CS_)];
        }
        g_X[idx] = v;
    } else if (idx < NX + NW) {
        int j = idx - NX;
        int n = j / KC, k = j % KC;
        g_Wc[j] = (k < IN_ + NS_ * CS_) ? W_ih[n * (IN_ + NS_ * CS_) + k]
                                        : W_hh[n * HH + (k - IN_ - NS_ * CS_)];
    } else if (idx < NX + NW + HH) {
        int n = idx - NX - NW;
        g_bc[n] = b_ih[n] + b_hh[n];
    } else if (idx < NX + NW + HH + NWPA) {
        int j = idx - (NX + NW + HH);
        int n = j / HH, k = j % HH;
        float v;
        if (n < 512)      v = W_push[n * HH + k];
        else if (n < 524) v = W_act[(n - 512) * HH + k];
        else              v = 0.f;
        g_Wpa[j] = v;
    } else if (idx < NX + NW + HH + NWPA + NPA) {
        int n = idx - (NX + NW + HH + NWPA);
        g_bpa[n] = (n < 512) ? b_push[n] : ((n < 524) ? b_act[n - 512] : 0.f);
    }
}

// ---------------------------------------------------------------------------
// GEMM: C[M, N] = act(A[M,K] @ W[N,K]^T + bias)
// BM=32, BN=64, BK=16, 128 threads, 4x4 per thread, reg-prefetch pipeline.
// MODE 0: tanh, write C (ld=HH)
// MODE 1: no act; tile n0<512 -> C (push, ld=HH); n0==512 -> C2 logits (ld=12)
// ---------------------------------------------------------------------------
template <int MODE>
__global__ void __launch_bounds__(128)
gemm4x4(const float* __restrict__ A, const float* __restrict__ W,
        const float* __restrict__ bias, float* __restrict__ C,
        float* __restrict__ C2, int K) {
    __shared__ __align__(16) float As[16][36];   // [k][m], 144B row stride (16B mult)
    __shared__ __align__(16) float Bs[16][68];   // [k][n], 272B row stride (16B mult)

    const int tid = threadIdx.x;
    const int m0 = blockIdx.y * 32;
    const int n0 = blockIdx.x * 64;
    const int lr = tid >> 2;             // 0..31
    const int lc = (tid & 3) << 2;       // 0,4,8,12
    const int tx = tid & 15;             // n-thread (x4)
    const int ty = tid >> 4;             // m-thread (x4)

    float acc[4][4] = {};

    const float* Arow  = A + (m0 + lr) * K + lc;
    const float* Wrow0 = W + (n0 + lr) * K + lc;
    const float* Wrow1 = W + (n0 + lr + 32) * K + lc;

    float4 va  = *(const float4*)(Arow);
    float4 vb0 = *(const float4*)(Wrow0);
    float4 vb1 = *(const float4*)(Wrow1);

    for (int k0 = 0; k0 < K; k0 += 16) {
        As[lc + 0][lr] = va.x;  As[lc + 1][lr] = va.y;
        As[lc + 2][lr] = va.z;  As[lc + 3][lr] = va.w;
        Bs[lc + 0][lr] = vb0.x; Bs[lc + 1][lr] = vb0.y;
        Bs[lc + 2][lr] = vb0.z; Bs[lc + 3][lr] = vb0.w;
        Bs[lc + 0][lr + 32] = vb1.x; Bs[lc + 1][lr + 32] = vb1.y;
        Bs[lc + 2][lr + 32] = vb1.z; Bs[lc + 3][lr + 32] = vb1.w;
        __syncthreads();

        if (k0 + 16 < K) {
            va  = *(const float4*)(Arow  + k0 + 16);
            vb0 = *(const float4*)(Wrow0 + k0 + 16);
            vb1 = *(const float4*)(Wrow1 + k0 + 16);
        }

        #pragma unroll
        for (int kk = 0; kk < 16; ++kk) {
            float4 a = *(const float4*)&As[kk][ty * 4];
            float4 b = *(const float4*)&Bs[kk][tx * 4];
            acc[0][0] = fmaf(a.x, b.x, acc[0][0]);
            acc[0][1] = fmaf(a.x, b.y, acc[0][1]);
            acc[0][2] = fmaf(a.x, b.z, acc[0][2]);
            acc[0][3] = fmaf(a.x, b.w, acc[0][3]);
            acc[1][0] = fmaf(a.y, b.x, acc[1][0]);
            acc[1][1] = fmaf(a.y, b.y, acc[1][1]);
            acc[1][2] = fmaf(a.y, b.z, acc[1][2]);
            acc[1][3] = fmaf(a.y, b.w, acc[1][3]);
            acc[2][0] = fmaf(a.z, b.x, acc[2][0]);
            acc[2][1] = fmaf(a.z, b.y, acc[2][1]);
            acc[2][2] = fmaf(a.z, b.z, acc[2][2]);
            acc[2][3] = fmaf(a.z, b.w, acc[2][3]);
            acc[3][0] = fmaf(a.w, b.x, acc[3][0]);
            acc[3][1] = fmaf(a.w, b.y, acc[3][1]);
            acc[3][2] = fmaf(a.w, b.z, acc[3][2]);
            acc[3][3] = fmaf(a.w, b.w, acc[3][3]);
        }
        __syncthreads();
    }

    const int nbase = n0 + tx * 4;
    float bi0 = bias[nbase + 0], bi1 = bias[nbase + 1];
    float bi2 = bias[nbase + 2], bi3 = bias[nbase + 3];

    #pragma unroll
    for (int i = 0; i < 4; ++i) {
        const int m = m0 + ty * 4 + i;
        if (MODE == 0) {
            float4 o;
            o.x = tanhf(acc[i][0] + bi0);
            o.y = tanhf(acc[i][1] + bi1);
            o.z = tanhf(acc[i][2] + bi2);
            o.w = tanhf(acc[i][3] + bi3);
            *(float4*)(C + m * HH + nbase) = o;
        } else {
            if (n0 < 512) {
                float4 o;
                o.x = acc[i][0] + bi0;
                o.y = acc[i][1] + bi1;
                o.z = acc[i][2] + bi2;
                o.w = acc[i][3] + bi3;
                *(float4*)(C + m * HH + nbase) = o;
            } else {
                // logits region: global cols 512..523
                #pragma unroll
                for (int j = 0; j < 4; ++j) {
                    int c = tx * 4 + j;              // 0..63 within tile
                    if (c < 12)
                        C2[m * 12 + c] = acc[i][j] + bias[512 + c];
                }
            }
        }
    }
}

// ---------------------------------------------------------------------------
// Stack update (float4): block = 4 warps, warp w handles g = b*4 + w.
// Softmax over all 12 logits done per-thread (broadcast loads, trivial cost).
//   new[0] = pa*push + po*S[1] + no*S[0]
//   new[i] = pa*S[i-1] + po*S[i+1] + no*S[i]  (S[SS]=0)
// ---------------------------------------------------------------------------
__device__ __forceinline__ float4 f4mix(float pa, const float4 x,
                                        float po, const float4 y,
                                        float pn, const float4 z) {
    float4 r;
    r.x = fmaf(pa, x.x, fmaf(po, y.x, pn * z.x));
    r.y = fmaf(pa, x.y, fmaf(po, y.y, pn * z.y));
    r.z = fmaf(pa, x.z, fmaf(po, y.z, pn * z.z));
    r.w = fmaf(pa, x.w, fmaf(po, y.w, pn * z.w));
    return r;
}

__global__ void __launch_bounds__(128)
stack_kernel(const float* __restrict__ stacks,
             const float* __restrict__ push,
             const float* __restrict__ logits,
             float* __restrict__ out) {
    const int b    = blockIdx.x;
    const int ns   = threadIdx.x >> 5;
    const int lane = threadIdx.x & 31;
    const int g    = b * NS_ + ns;

    // joint softmax over 12 logits of batch b
    float l[12];
    #pragma unroll
    for (int i = 0; i < 12; ++i) l[i] = __ldg(&logits[b * 12 + i]);
    float mx = l[0];
    #pragma unroll
    for (int i = 1; i < 12; ++i) mx = fmaxf(mx, l[i]);
    float s = 0.f;
    #pragma unroll
    for (int i = 0; i < 12; ++i) { l[i] = expf(l[i] - mx); s += l[i]; }
    const float inv = 1.f / s;
    const float pa = l[ns * 3 + 0] * inv;
    const float po = l[ns * 3 + 1] * inv;
    const float no = l[ns * 3 + 2] * inv;

    const float4* S = (const float4*)stacks + (size_t)g * SS_ * 32 + lane;
    float4*       O = (float4*)out          + (size_t)g * SS_ * 32 + lane;
    const float4 pu = ((const float4*)push)[g * 32 + lane];

    float4 cur = S[0];
    float4 nxt = S[32];
    O[0] = f4mix(pa, pu, po, nxt, no, cur);

    #pragma unroll 6
    for (int i = 1; i < SS_ - 1; ++i) {
        float4 prev = cur;
        cur = nxt;
        nxt = S[(i + 1) * 32];
        O[i * 32] = f4mix(pa, prev, po, nxt, no, cur);
    }
    // i = SS-1: S[SS] = 0
    {
        float4 prev = cur;
        cur = nxt;
        float4 zero = make_float4(0.f, 0.f, 0.f, 0.f);
        O[(SS_ - 1) * 32] = f4mix(pa, prev, po, zero, no, cur);
    }
}

// ---------------------------------------------------------------------------
// Launch
// ---------------------------------------------------------------------------
extern "C" void kernel_launch(void* const* d_in, const int* in_sizes, int n_in,
                              void* d_out, int out_size) {
    const float* inputs  = (const float*)d_in[0];
    const float* stacks  = (const float*)d_in[1];
    const float* core    = (const float*)d_in[2];
    const float* W_ih    = (const float*)d_in[3];
    const float* b_ih    = (const float*)d_in[4];
    const float* W_hh    = (const float*)d_in[5];
    const float* b_hh    = (const float*)d_in[6];
    const float* W_push  = (const float*)d_in[7];
    const float* b_push  = (const float*)d_in[8];
    const float* W_act   = (const float*)d_in[9];
    const float* b_act   = (const float*)d_in[10];

    float* out = (float*)d_out;
    float* h_out      = out;               // (B, H)
    float* stacks_out = out + BB * HH;     // (B, NS, SS, CS)

    float *pX, *pWc, *pbc, *pWpa, *pbpa, *ppush, *plog;
    cudaGetSymbolAddress((void**)&pX,    g_X);
    cudaGetSymbolAddress((void**)&pWc,   g_Wc);
    cudaGetSymbolAddress((void**)&pbc,   g_bc);
    cudaGetSymbolAddress((void**)&pWpa,  g_Wpa);
    cudaGetSymbolAddress((void**)&pbpa,  g_bpa);
    cudaGetSymbolAddress((void**)&ppush, g_push);
    cudaGetSymbolAddress((void**)&plog,  g_logits);

    // 0) assemble
    {
        int total = BB * KC + HH * KC + HH + NPA * HH + NPA;
        prep_kernel<<<(total + 255) / 256, 256>>>(inputs, stacks, core,
                                                  W_ih, W_hh, b_ih, b_hh,
                                                  W_push, b_push, W_act, b_act);
    }

    // 1) h = tanh(X @ Wc^T + bc)   grid (8, 16), 128 CTAs
    {
        dim3 grid(HH / 64, BB / 32);
        gemm4x4<0><<<grid, 128>>>(pX, pWc, pbc, h_out, nullptr, KC);
    }

    // 2) [push | logits] = h @ Wpa^T + bpa    grid (9, 16), 144 CTAs
    {
        dim3 grid(NPA / 64, BB / 32);
        gemm4x4<1><<<grid, 128>>>(h_out, pWpa, pbpa, ppush, plog, HH);
    }

    // 3) stack shift update (+ in-kernel softmax)
    stack_kernel<<<BB, 128>>>(stacks, ppush, plog, stacks_out);
}

// round 5
// speedup vs baseline: 1.5554x; 1.4012x over previous
#include <cuda_runtime.h>
#include <math.h>

#define BB   512
#define IN_  256
#define HH   512
#define NS_  4
#define SS_  128
#define CS_  128
#define KH   1280           // IN + NS*CS + HH
#define NPA  576            // 512 push + 12 act + 52 pad
#define KSPL 4              // split-K factor

// ---------------------------------------------------------------------------
// Scratch
// ---------------------------------------------------------------------------
__device__ __align__(16) float g_Ph  [KSPL * BB * HH];    // gemm-h partials
__device__ __align__(16) float g_Ppa [KSPL * BB * NPA];   // gemm-pa partials
__device__ __align__(16) float g_push[BB * NS_ * CS_];
__device__ __align__(16) float g_logits[BB * 12];
__device__ __align__(16) float g_probs [BB * 12];

__device__ __forceinline__ float tanh_fast(float x) {
    float y;
    asm("tanh.approx.f32 %0, %1;" : "=f"(y) : "f"(x));
    return y;
}

// ---------------------------------------------------------------------------
// Virtual operand loaders (float4, k % 4 == 0; region bounds are multiples
// of 16 so a BK=16 tile never straddles regions for A/W of gemm-h)
// ---------------------------------------------------------------------------
__device__ __forceinline__ float4 ldX(const float* __restrict__ inputs,
                                      const float* __restrict__ stacks,
                                      const float* __restrict__ core,
                                      int m, int k) {
    if (k < IN_) {
        return *(const float4*)(inputs + m * IN_ + k);
    } else if (k < IN_ + NS_ * CS_) {
        int c = k - IN_;
        return *(const float4*)(stacks + ((size_t)(m * NS_ + (c >> 7))) * (SS_ * CS_) + (c & 127));
    } else {
        return *(const float4*)(core + m * HH + (k - IN_ - NS_ * CS_));
    }
}

__device__ __forceinline__ float4 ldWc(const float* __restrict__ W_ih,
                                       const float* __restrict__ W_hh,
                                       int n, int k) {
    if (k < IN_ + NS_ * CS_)
        return *(const float4*)(W_ih + (size_t)n * (IN_ + NS_ * CS_) + k);
    else
        return *(const float4*)(W_hh + (size_t)n * HH + (k - IN_ - NS_ * CS_));
}

__device__ __forceinline__ float4 ldWpa(const float* __restrict__ W_push,
                                        const float* __restrict__ W_act,
                                        int n, int k) {
    if (n < 512)       return *(const float4*)(W_push + (size_t)n * HH + k);
    else if (n < 524)  return *(const float4*)(W_act + (size_t)(n - 512) * HH + k);
    else               return make_float4(0.f, 0.f, 0.f, 0.f);
}

// ---------------------------------------------------------------------------
// GEMM (split-K partials): P[z, m, n] = sum_{k in split z} A[m,k] * W[n,k]
// BM=64, BN=64, BK=16, 128 threads, 8x4 per thread.
// MODE 0: gemm-h   (A = virtual X,   W = [W_ih|W_hh],   N=512, K=1280)
// MODE 1: gemm-pa  (A = h,           W = [W_push;W_act;0], N=576, K=512)
// ---------------------------------------------------------------------------
template <int MODE>
__global__ void __launch_bounds__(128)
gemm_split(const float* __restrict__ Ah,
           const float* __restrict__ inputs,
           const float* __restrict__ stacks,
           const float* __restrict__ core,
           const float* __restrict__ W_ih,
           const float* __restrict__ W_hh,
           const float* __restrict__ W_push,
           const float* __restrict__ W_act,
           float* __restrict__ P) {
    __shared__ __align__(16) float As[16][68];
    __shared__ __align__(16) float Bs[16][68];

    constexpr int N  = (MODE == 0) ? HH : NPA;
    constexpr int NT = (MODE == 0) ? (KH / KSPL / 16) : (HH / KSPL / 16); // 20 / 8

    const int tid = threadIdx.x;
    const int m0 = blockIdx.y * 64;
    const int n0 = blockIdx.x * 64;
    const int z  = blockIdx.z;
    const int k0 = z * NT * 16;

    const int lr = tid >> 2;            // 0..31
    const int lc = (tid & 3) << 2;      // 0,4,8,12
    const int tx = tid & 15;            // n (x4)
    const int ty = tid >> 4;            // m (x8)

    float acc[8][4] = {};

    // prefetch tile 0
    float4 a0, a1, b0, b1;
    {
        int k = k0 + lc;
        if (MODE == 0) {
            a0 = ldX(inputs, stacks, core, m0 + lr, k);
            a1 = ldX(inputs, stacks, core, m0 + lr + 32, k);
            b0 = ldWc(W_ih, W_hh, n0 + lr, k);
            b1 = ldWc(W_ih, W_hh, n0 + lr + 32, k);
        } else {
            a0 = *(const float4*)(Ah + (m0 + lr) * HH + k);
            a1 = *(const float4*)(Ah + (m0 + lr + 32) * HH + k);
            b0 = ldWpa(W_push, W_act, n0 + lr, k);
            b1 = ldWpa(W_push, W_act, n0 + lr + 32, k);
        }
    }

    for (int kt = 0; kt < NT; ++kt) {
        As[lc + 0][lr] = a0.x; As[lc + 1][lr] = a0.y;
        As[lc + 2][lr] = a0.z; As[lc + 3][lr] = a0.w;
        As[lc + 0][lr + 32] = a1.x; As[lc + 1][lr + 32] = a1.y;
        As[lc + 2][lr + 32] = a1.z; As[lc + 3][lr + 32] = a1.w;
        Bs[lc + 0][lr] = b0.x; Bs[lc + 1][lr] = b0.y;
        Bs[lc + 2][lr] = b0.z; Bs[lc + 3][lr] = b0.w;
        Bs[lc + 0][lr + 32] = b1.x; Bs[lc + 1][lr + 32] = b1.y;
        Bs[lc + 2][lr + 32] = b1.z; Bs[lc + 3][lr + 32] = b1.w;
        __syncthreads();

        if (kt + 1 < NT) {
            int k = k0 + (kt + 1) * 16 + lc;
            if (MODE == 0) {
                a0 = ldX(inputs, stacks, core, m0 + lr, k);
                a1 = ldX(inputs, stacks, core, m0 + lr + 32, k);
                b0 = ldWc(W_ih, W_hh, n0 + lr, k);
                b1 = ldWc(W_ih, W_hh, n0 + lr + 32, k);
            } else {
                a0 = *(const float4*)(Ah + (m0 + lr) * HH + k);
                a1 = *(const float4*)(Ah + (m0 + lr + 32) * HH + k);
                b0 = ldWpa(W_push, W_act, n0 + lr, k);
                b1 = ldWpa(W_push, W_act, n0 + lr + 32, k);
            }
        }

        #pragma unroll
        for (int kk = 0; kk < 16; ++kk) {
            float ar[8], br[4];
            *reinterpret_cast<float4*>(&ar[0]) = *(const float4*)&As[kk][ty * 8];
            *reinterpret_cast<float4*>(&ar[4]) = *(const float4*)&As[kk][ty * 8 + 4];
            *reinterpret_cast<float4*>(&br[0]) = *(const float4*)&Bs[kk][tx * 4];
            #pragma unroll
            for (int i = 0; i < 8; ++i)
                #pragma unroll
                for (int j = 0; j < 4; ++j)
                    acc[i][j] = fmaf(ar[i], br[j], acc[i][j]);
        }
        __syncthreads();
    }

    float* Pz = P + (size_t)z * BB * N;
    #pragma unroll
    for (int i = 0; i < 8; ++i) {
        float4 o = make_float4(acc[i][0], acc[i][1], acc[i][2], acc[i][3]);
        *(float4*)(Pz + (m0 + ty * 8 + i) * N + n0 + tx * 4) = o;
    }
}

// ---------------------------------------------------------------------------
// Epilogue h: h = tanh(sum_z P[z] + b_ih + b_hh)
// ---------------------------------------------------------------------------
__global__ void __launch_bounds__(256)
epi_h(const float* __restrict__ P,
      const float* __restrict__ b_ih, const float* __restrict__ b_hh,
      float* __restrict__ h) {
    int idx = blockIdx.x * 256 + threadIdx.x;   // float4 index, 65536 total
    int e = idx << 2;
    int n = e & (HH - 1);
    float4 s = *(const float4*)(P + e);
    float4 s1 = *(const float4*)(P + BB * HH + e);
    float4 s2 = *(const float4*)(P + 2 * BB * HH + e);
    float4 s3 = *(const float4*)(P + 3 * BB * HH + e);
    float4 bi = *(const float4*)(b_ih + n);
    float4 bh = *(const float4*)(b_hh + n);
    float4 o;
    o.x = tanh_fast(s.x + s1.x + s2.x + s3.x + bi.x + bh.x);
    o.y = tanh_fast(s.y + s1.y + s2.y + s3.y + bi.y + bh.y);
    o.z = tanh_fast(s.z + s1.z + s2.z + s3.z + bi.z + bh.z);
    o.w = tanh_fast(s.w + s1.w + s2.w + s3.w + bi.w + bh.w);
    *(float4*)(h + e) = o;
}

// ---------------------------------------------------------------------------
// Epilogue pa: push = sum_z Q[z] + b_push (n<512), logits = ... + b_act (512..523)
// ---------------------------------------------------------------------------
__global__ void __launch_bounds__(256)
epi_pa(const float* __restrict__ Q,
       const float* __restrict__ b_push, const float* __restrict__ b_act,
       float* __restrict__ push, float* __restrict__ logits) {
    int idx = blockIdx.x * 256 + threadIdx.x;   // float4 index over 512*576
    int e = idx << 2;
    int m = e / NPA;
    int n = e - m * NPA;
    if (n >= 524) return;
    float4 s = *(const float4*)(Q + e);
    float4 s1 = *(const float4*)(Q + BB * NPA + e);
    float4 s2 = *(const float4*)(Q + 2 * BB * NPA + e);
    float4 s3 = *(const float4*)(Q + 3 * BB * NPA + e);
    float4 o;
    o.x = s.x + s1.x + s2.x + s3.x;
    o.y = s.y + s1.y + s2.y + s3.y;
    o.z = s.z + s1.z + s2.z + s3.z;
    o.w = s.w + s1.w + s2.w + s3.w;
    if (n < 512) {
        float4 b = *(const float4*)(b_push + n);
        o.x += b.x; o.y += b.y; o.z += b.z; o.w += b.w;
        *(float4*)(push + m * 512 + n) = o;
    } else {
        float4 b = *(const float4*)(b_act + (n - 512));
        o.x += b.x; o.y += b.y; o.z += b.z; o.w += b.w;
        *(float4*)(logits + m * 12 + (n - 512)) = o;
    }
}

// ---------------------------------------------------------------------------
// probs: joint softmax over 12 logits per batch row (once, not per stack thread)
// ---------------------------------------------------------------------------
__global__ void __launch_bounds__(256)
probs_kernel(const float* __restrict__ logits, float* __restrict__ probs) {
    int b = blockIdx.x * 256 + threadIdx.x;
    if (b >= BB) return;
    float l[12];
    #pragma unroll
    for (int i = 0; i < 12; ++i) l[i] = logits[b * 12 + i];
    float mx = l[0];
    #pragma unroll
    for (int i = 1; i < 12; ++i) mx = fmaxf(mx, l[i]);
    float s = 0.f;
    #pragma unroll
    for (int i = 0; i < 12; ++i) { l[i] = expf(l[i] - mx); s += l[i]; }
    float inv = 1.f / s;
    #pragma unroll
    for (int i = 0; i < 12; ++i) probs[b * 12 + i] = l[i] * inv;
}

// ---------------------------------------------------------------------------
// Stack update v2: segment-batched. Thread = (g, col4, 8-row segment).
// grid 4096 = (g * 2 halves), block 256 = 32 cols x 8 segs.
//   new[0] = pa*push + po*S[1] + no*S[0]
//   new[i] = pa*S[i-1] + po*S[i+1] + no*S[i]   (S[128]=0)
// ---------------------------------------------------------------------------
__device__ __forceinline__ float4 f4mix(float pa, const float4 x,
                                        float po, const float4 y,
                                        float pn, const float4 z) {
    float4 r;
    r.x = fmaf(pa, x.x, fmaf(po, y.x, pn * z.x));
    r.y = fmaf(pa, x.y, fmaf(po, y.y, pn * z.y));
    r.z = fmaf(pa, x.z, fmaf(po, y.z, pn * z.z));
    r.w = fmaf(pa, x.w, fmaf(po, y.w, pn * z.w));
    return r;
}

__global__ void __launch_bounds__(256)
stack_kernel(const float* __restrict__ stacks,
             const float* __restrict__ push,
             const float* __restrict__ probs,
             float* __restrict__ out) {
    const int g    = blockIdx.x >> 1;
    const int half = blockIdx.x & 1;
    const int seg  = threadIdx.x >> 5;
    const int col  = threadIdx.x & 31;
    const int rb   = half * 64 + seg * 8;     // 0..120 step 8

    const int b  = g >> 2;
    const int ns = g & 3;
    const float pa = __ldg(&probs[b * 12 + ns * 3 + 0]);
    const float po = __ldg(&probs[b * 12 + ns * 3 + 1]);
    const float no = __ldg(&probs[b * 12 + ns * 3 + 2]);

    const float4* S = (const float4*)stacks + (size_t)g * (SS_ * 32) + col;
    float4*       O = (float4*)out          + (size_t)g * (SS_ * 32) + col;
    const float4  pu = ((const float4*)push)[g * 32 + col];

    float4 v[10];
    v[0] = (rb == 0) ? pu : S[(rb - 1) * 32];
    #pragma unroll
    for (int j = 1; j <= 8; ++j) v[j] = S[(rb + j - 1) * 32];
    v[9] = (rb == 120) ? make_float4(0.f, 0.f, 0.f, 0.f) : S[(rb + 8) * 32];

    #pragma unroll
    for (int i = 0; i < 8; ++i)
        O[(rb + i) * 32] = f4mix(pa, v[i], po, v[i + 2], no, v[i + 1]);
}

// ---------------------------------------------------------------------------
// Launch
// ---------------------------------------------------------------------------
extern "C" void kernel_launch(void* const* d_in, const int* in_sizes, int n_in,
                              void* d_out, int out_size) {
    const float* inputs  = (const float*)d_in[0];
    const float* stacks  = (const float*)d_in[1];
    const float* core    = (const float*)d_in[2];
    const float* W_ih    = (const float*)d_in[3];
    const float* b_ih    = (const float*)d_in[4];
    const float* W_hh    = (const float*)d_in[5];
    const float* b_hh    = (const float*)d_in[6];
    const float* W_push  = (const float*)d_in[7];
    const float* b_push  = (const float*)d_in[8];
    const float* W_act   = (const float*)d_in[9];
    const float* b_act   = (const float*)d_in[10];

    float* out = (float*)d_out;
    float* h_out      = out;               // (B, H)
    float* stacks_out = out + BB * HH;     // (B, NS, SS, CS)

    float *pPh, *pPpa, *ppush, *plog, *pprob;
    cudaGetSymbolAddress((void**)&pPh,   g_Ph);
    cudaGetSymbolAddress((void**)&pPpa,  g_Ppa);
    cudaGetSymbolAddress((void**)&ppush, g_push);
    cudaGetSymbolAddress((void**)&plog,  g_logits);
    cudaGetSymbolAddress((void**)&pprob, g_probs);

    // 1) gemm-h partials:  grid (8,8,4) = 256 CTAs
    gemm_split<0><<<dim3(HH / 64, BB / 64, KSPL), 128>>>(
        nullptr, inputs, stacks, core, W_ih, W_hh, nullptr, nullptr, pPh);

    // 2) h = tanh(sum + biases)
    epi_h<<<BB * HH / 4 / 256, 256>>>(pPh, b_ih, b_hh, h_out);

    // 3) gemm-pa partials: grid (9,8,4) = 288 CTAs
    gemm_split<1><<<dim3(NPA / 64, BB / 64, KSPL), 128>>>(
        h_out, nullptr, nullptr, nullptr, nullptr, nullptr, W_push, W_act, pPpa);

    // 4) push + logits
    epi_pa<<<BB * NPA / 4 / 256, 256>>>(pPpa, b_push, b_act, ppush, plog);

    // 5) softmax probs (once)
    probs_kernel<<<2, 256>>>(plog, pprob);

    // 6) stack shift update
    stack_kernel<<<BB * NS_ * 2, 256>>>(stacks, ppush, pprob, stacks_out);
}